// round 1
// baseline (speedup 1.0000x reference)
#include <cuda_runtime.h>
#include <cstdint>

#define N_PTS   16384
#define THREADS 256
#define IPT     4                    // set1 points per thread (2 packed f32x2 pairs)
#define I_SPAN  (THREADS * IPT)      // 1024 points per i-block
#define JCHUNK  1024                 // set2 points per j-chunk (32KB smem tile)
#define NBLK_I  (N_PTS / I_SPAN)     // 16
#define NBLK_J  (N_PTS / JCHUNK)     // 16

// Scratch (no cudaMalloc allowed): duplicated-operand form of both point sets,
// squared norms, and per-point min-d^2 accumulators (as uint bits).
__device__ float4   g_dup[2][2 * N_PTS];
__device__ float    g_sq [2][N_PTS];
__device__ unsigned g_min[2][N_PTS];

// ---------------------------------------------------------------------------
// f32x2 helpers (Blackwell packed fp32 pipe)
// ---------------------------------------------------------------------------
__device__ __forceinline__ uint64_t pack2(float lo, float hi) {
    uint64_t r;
    asm("mov.b64 %0, {%1, %2};" : "=l"(r) : "f"(lo), "f"(hi));
    return r;
}
__device__ __forceinline__ void unpack2(uint64_t v, float& lo, float& hi) {
    asm("mov.b64 {%0, %1}, %2;" : "=f"(lo), "=f"(hi) : "l"(v));
}
__device__ __forceinline__ uint64_t ffma2(uint64_t a, uint64_t b, uint64_t c) {
    uint64_t d;
    asm("fma.rn.f32x2 %0, %1, %2, %3;" : "=l"(d) : "l"(a), "l"(b), "l"(c));
    return d;
}

// ---------------------------------------------------------------------------
// Pass 1: build b' = (-2x,-2x,-2y,-2y | -2z,-2z,|b|^2,|b|^2) for both sets,
// init min accumulators to +inf, zero the output scalar.
// ---------------------------------------------------------------------------
__global__ void prep_kernel(const float* __restrict__ s1,
                            const float* __restrict__ s2,
                            float* __restrict__ out) {
    int i = blockIdx.x * blockDim.x + threadIdx.x;
    if (i == 0) *out = 0.0f;
    if (i >= N_PTS) return;
    const float* srcs[2] = { s1, s2 };
#pragma unroll
    for (int s = 0; s < 2; s++) {
        float x = srcs[s][3 * i + 0];
        float y = srcs[s][3 * i + 1];
        float z = srcs[s][3 * i + 2];
        float sq = x * x + y * y + z * z;
        g_dup[s][2 * i + 0] = make_float4(-2.f * x, -2.f * x, -2.f * y, -2.f * y);
        g_dup[s][2 * i + 1] = make_float4(-2.f * z, -2.f * z, sq, sq);
        g_sq [s][i] = sq;
        g_min[s][i] = 0x7F800000u;   // +inf bits
    }
}

// ---------------------------------------------------------------------------
// Pass 2: for direction dir (blockIdx.y), A = set[dir], B = set[1-dir].
// Block = (i-block, dir, j-chunk). Each thread owns 4 A-points, scans the
// SMEM j-tile computing val = |b|^2 - 2 a.b via 3 packed FFMA2 per 2 pairs,
// running min in registers, then atomicMin(d^2 bits) to global.
// ---------------------------------------------------------------------------
__global__ void __launch_bounds__(THREADS)
hausdorff_main(const float* __restrict__ s1, const float* __restrict__ s2) {
    __shared__ ulonglong2 tile[2 * JCHUNK];   // 32KB: per j -> (bx2,by2)(bz2,bsq2)

    const int dir = blockIdx.y;
    const float* A = dir ? s2 : s1;
    const int jbase = blockIdx.z * JCHUNK;

    // Load duplicated B' tile into shared
    {
        const float4* src = &g_dup[1 - dir][2 * jbase];
        float4* dst = reinterpret_cast<float4*>(tile);
        for (int t = threadIdx.x; t < 2 * JCHUNK; t += THREADS) dst[t] = src[t];
    }
    __syncthreads();

    const int ibase = blockIdx.x * I_SPAN + threadIdx.x;

    uint64_t ax2[2], ay2[2], az2[2];
    float asq[IPT];
#pragma unroll
    for (int p = 0; p < 2; p++) {
        int i0 = ibase + (2 * p + 0) * THREADS;
        int i1 = ibase + (2 * p + 1) * THREADS;
        ax2[p] = pack2(A[3 * i0 + 0], A[3 * i1 + 0]);
        ay2[p] = pack2(A[3 * i0 + 1], A[3 * i1 + 1]);
        az2[p] = pack2(A[3 * i0 + 2], A[3 * i1 + 2]);
        asq[2 * p + 0] = g_sq[dir][i0];
        asq[2 * p + 1] = g_sq[dir][i1];
    }

    float m[IPT] = { INFINITY, INFINITY, INFINITY, INFINITY };

#pragma unroll 4
    for (int j = 0; j < JCHUNK; j++) {
        ulonglong2 q0 = tile[2 * j + 0];   // (bx2, by2)
        ulonglong2 q1 = tile[2 * j + 1];   // (bz2, bsq2)
#pragma unroll
        for (int p = 0; p < 2; p++) {
            uint64_t acc = ffma2(az2[p], q1.x, q1.y);
            acc = ffma2(ay2[p], q0.y, acc);
            acc = ffma2(ax2[p], q0.x, acc);
            float v0, v1;
            unpack2(acc, v0, v1);
            m[2 * p + 0] = fminf(m[2 * p + 0], v0);
            m[2 * p + 1] = fminf(m[2 * p + 1], v1);
        }
    }

    unsigned* mins = g_min[dir];
#pragma unroll
    for (int k = 0; k < IPT; k++) {
        int i = ibase + k * THREADS;
        float d2 = fmaxf(m[k] + asq[k], 0.0f);   // clamp cancellation noise; >=0 => uint-ordered
        atomicMin(&mins[i], __float_as_uint(d2));
    }
}

// ---------------------------------------------------------------------------
// Pass 3: per direction, mean of sqrt(min d^2); sum both into out.
// ---------------------------------------------------------------------------
__global__ void reduce_kernel(float* __restrict__ out) {
    __shared__ float red[1024];
    const int dir = blockIdx.x;
    float s = 0.0f;
    for (int i = threadIdx.x; i < N_PTS; i += 1024)
        s += sqrtf(__uint_as_float(g_min[dir][i]));
    red[threadIdx.x] = s;
    __syncthreads();
    for (int w = 512; w > 0; w >>= 1) {
        if (threadIdx.x < w) red[threadIdx.x] += red[threadIdx.x + w];
        __syncthreads();
    }
    if (threadIdx.x == 0) atomicAdd(out, red[0] * (1.0f / N_PTS));
}

// ---------------------------------------------------------------------------
extern "C" void kernel_launch(void* const* d_in, const int* in_sizes, int n_in,
                              void* d_out, int out_size) {
    const float* s1 = (const float*)d_in[0];
    const float* s2 = (const float*)d_in[1];
    float* out = (float*)d_out;

    prep_kernel<<<N_PTS / 256, 256>>>(s1, s2, out);
    dim3 grid(NBLK_I, 2, NBLK_J);
    hausdorff_main<<<grid, THREADS>>>(s1, s2);
    reduce_kernel<<<2, 1024>>>(out);
}